// round 1
// baseline (speedup 1.0000x reference)
#include <cuda_runtime.h>
#include <cstddef>

#define N_NODES 50000
#define N_EDGES 800000
#define IN_C 128
#define HID_C 128
#define OUT_C 64

// ---------------- scratch (device globals: allocation-free rule) ----------------
__device__ __align__(16) float g_y1  [N_NODES * HID_C];   // x @ W_l1^T
__device__ __align__(16) float g_agg1[N_NODES * HID_C];   // scatter-sum of w*y1[src]
__device__ __align__(16) float g_h   [N_NODES * HID_C];   // layer-1 output
__device__ __align__(16) float g_y2  [N_NODES * OUT_C];   // h @ W_l2^T
__device__ __align__(16) float g_agg2[N_NODES * OUT_C];
__device__ __align__(16) float g_deg [N_NODES];

// ---------------- zeroing (graph-capturable, no memset API needed) --------------
__global__ void zero_kernel() {
    int tid = blockIdx.x * blockDim.x + threadIdx.x;
    int stride = gridDim.x * blockDim.x;
    float4 z = make_float4(0.f, 0.f, 0.f, 0.f);
    float4* a1 = reinterpret_cast<float4*>(g_agg1);
    float4* a2 = reinterpret_cast<float4*>(g_agg2);
    for (int i = tid; i < N_NODES * HID_C / 4; i += stride) a1[i] = z;
    for (int i = tid; i < N_NODES * OUT_C / 4; i += stride) a2[i] = z;
    for (int i = tid; i < N_NODES; i += stride) g_deg[i] = 0.f;
}

// ---------------- degree ---------------------------------------------------------
__global__ void deg_kernel(const int* __restrict__ dst) {
    int e = blockIdx.x * blockDim.x + threadIdx.x;
    if (e < N_EDGES) atomicAdd(&g_deg[dst[e]], 1.0f);
}

// ---------------- edge aggregation: agg[dst] += w * y[src], vectorized red ------
template <int C>
__global__ void edge_agg_kernel(const float* __restrict__ y,
                                const int* __restrict__ src,
                                const int* __restrict__ dst,
                                const float* __restrict__ ew,
                                float* __restrict__ agg) {
    constexpr int TPE = C / 4;                 // threads per edge (float4 each)
    int tid = blockIdx.x * blockDim.x + threadIdx.x;
    int e = tid / TPE;
    int j = tid % TPE;
    if (e >= N_EDGES) return;
    int s = src[e];
    int d = dst[e];
    float w = ew[e];
    float4 v = *reinterpret_cast<const float4*>(y + (size_t)s * C + j * 4);
    float* addr = agg + (size_t)d * C + j * 4;
    asm volatile("red.global.add.v4.f32 [%0], {%1, %2, %3, %4};"
                 :: "l"(addr), "f"(v.x * w), "f"(v.y * w), "f"(v.z * w), "f"(v.w * w)
                 : "memory");
}

// ---------------- fused linear: out = [relu]( A@W^T (+ bias + agg/deg) ) --------
// A: [n,128] row-major, W: [BN,128] row-major. BM=64, full N tile, KC=32 chunks.
template <int BN, bool EPI, bool RELU>
__global__ void __launch_bounds__(256)
linear_kernel(const float* __restrict__ A, const float* __restrict__ W,
              const float* __restrict__ bias, const float* __restrict__ agg,
              const float* __restrict__ deg, float* __restrict__ out, int n) {
    constexpr int BM = 64, K = 128, KC = 32;
    constexpr int TN = BN / 16;                      // 8 for BN=128, 4 for BN=64
    __shared__ float As[KC][68];                     // k-major, padded (16B-aligned rows, no STS conflicts)
    __shared__ float Ws[KC][BN + 4];

    int row0 = blockIdx.x * BM;
    int tid = threadIdx.x;
    int tr = tid >> 4;                               // 0..15 row group (4 rows)
    int tc = tid & 15;                               // 0..15 col group (TN cols)

    float acc[4][TN];
#pragma unroll
    for (int i = 0; i < 4; i++)
#pragma unroll
        for (int j = 0; j < TN; j++) acc[i][j] = 0.f;

    for (int kc = 0; kc < K; kc += KC) {
        // --- load A tile (coalesced: 8 lanes span one row's 128B) ---
#pragma unroll
        for (int it = 0; it < 2; it++) {
            int idx = tid + it * 256;                // 0..511
            int row = idx >> 3;
            int k4  = idx & 7;
            float4 v = make_float4(0.f, 0.f, 0.f, 0.f);
            if (row0 + row < n)
                v = *reinterpret_cast<const float4*>(A + (size_t)(row0 + row) * K + kc + k4 * 4);
            As[k4 * 4 + 0][row] = v.x;
            As[k4 * 4 + 1][row] = v.y;
            As[k4 * 4 + 2][row] = v.z;
            As[k4 * 4 + 3][row] = v.w;
        }
        // --- load W tile ---
#pragma unroll
        for (int it = 0; it < BN * 8 / 256; it++) {
            int idx = tid + it * 256;
            int c  = idx >> 3;
            int k4 = idx & 7;
            float4 v = *reinterpret_cast<const float4*>(W + (size_t)c * K + kc + k4 * 4);
            Ws[k4 * 4 + 0][c] = v.x;
            Ws[k4 * 4 + 1][c] = v.y;
            Ws[k4 * 4 + 2][c] = v.z;
            Ws[k4 * 4 + 3][c] = v.w;
        }
        __syncthreads();
        // --- compute ---
#pragma unroll
        for (int k = 0; k < KC; k++) {
            float4 a = *reinterpret_cast<const float4*>(&As[k][tr * 4]);
            float av[4] = {a.x, a.y, a.z, a.w};
            float bv[TN];
#pragma unroll
            for (int j0 = 0; j0 < TN; j0 += 4) {
                float4 b = *reinterpret_cast<const float4*>(&Ws[k][tc * TN + j0]);
                bv[j0 + 0] = b.x; bv[j0 + 1] = b.y; bv[j0 + 2] = b.z; bv[j0 + 3] = b.w;
            }
#pragma unroll
            for (int i = 0; i < 4; i++)
#pragma unroll
                for (int j = 0; j < TN; j++)
                    acc[i][j] = fmaf(av[i], bv[j], acc[i][j]);
        }
        __syncthreads();
    }

    // --- epilogue ---
#pragma unroll
    for (int i = 0; i < 4; i++) {
        int r = row0 + tr * 4 + i;
        if (r >= n) continue;
        float invd = 0.f;
        if constexpr (EPI) invd = 1.0f / fmaxf(deg[r], 1.0f);
#pragma unroll
        for (int j = 0; j < TN; j++) {
            int c = tc * TN + j;
            float v = acc[i][j];
            if constexpr (EPI) v += bias[c] + agg[(size_t)r * BN + c] * invd;
            if constexpr (RELU) v = fmaxf(v, 0.f);
            out[(size_t)r * BN + c] = v;
        }
    }
}

// ---------------- launch --------------------------------------------------------
extern "C" void kernel_launch(void* const* d_in, const int* in_sizes, int n_in,
                              void* d_out, int out_size) {
    const float* x    = (const float*)d_in[0];
    const int*   ei   = (const int*)  d_in[1];
    const float* ew   = (const float*)d_in[2];
    // d_in[3] = node_type (unused by the reference)
    const float* W_l1 = (const float*)d_in[4];
    const float* b_l1 = (const float*)d_in[5];
    const float* W_r1 = (const float*)d_in[6];
    const float* W_l2 = (const float*)d_in[7];
    const float* b_l2 = (const float*)d_in[8];
    const float* W_r2 = (const float*)d_in[9];
    float* out = (float*)d_out;

    const int* src = ei;
    const int* dst = ei + N_EDGES;

    float *y1, *agg1, *h, *y2, *agg2, *deg;
    cudaGetSymbolAddress((void**)&y1,   g_y1);
    cudaGetSymbolAddress((void**)&agg1, g_agg1);
    cudaGetSymbolAddress((void**)&h,    g_h);
    cudaGetSymbolAddress((void**)&y2,   g_y2);
    cudaGetSymbolAddress((void**)&agg2, g_agg2);
    cudaGetSymbolAddress((void**)&deg,  g_deg);

    const int GEMM_BLOCKS = (N_NODES + 63) / 64;  // 782

    zero_kernel<<<2048, 256>>>();
    deg_kernel<<<(N_EDGES + 255) / 256, 256>>>(dst);

    // Layer 1: project first (linearity), aggregate, then fuse root-GEMM + epilogue
    linear_kernel<128, false, false><<<GEMM_BLOCKS, 256>>>(x, W_l1, nullptr, nullptr, nullptr, y1, N_NODES);
    edge_agg_kernel<128><<<N_EDGES * (128 / 4) / 256, 256>>>(y1, src, dst, ew, agg1);
    linear_kernel<128, true, true><<<GEMM_BLOCKS, 256>>>(x, W_r1, b_l1, agg1, deg, h, N_NODES);

    // Layer 2: project to 64 dims BEFORE aggregating (halves edge traffic)
    linear_kernel<64, false, false><<<GEMM_BLOCKS, 256>>>(h, W_l2, nullptr, nullptr, nullptr, y2, N_NODES);
    edge_agg_kernel<64><<<N_EDGES * (64 / 4) / 256, 256>>>(y2, src, dst, ew, agg2);
    linear_kernel<64, true, false><<<GEMM_BLOCKS, 256>>>(h, W_r2, b_l2, agg2, deg, out, N_NODES);
}

// round 2
// speedup vs baseline: 1.3544x; 1.3544x over previous
#include <cuda_runtime.h>
#include <cstddef>

#define N_NODES 50000
#define N_EDGES 800000
#define IN_C 128
#define HID_C 128
#define OUT_C 64
#define SCAN_BLOCKS 196   // ceil(50000/256)

// ---------------- scratch (device globals: allocation-free rule) ----------------
__device__ int   g_cnt [N_NODES];
__device__ int   g_pre [N_NODES];
__device__ int   g_bsum[256];
__device__ int   g_boff[256];
__device__ int   g_rowptr[N_NODES + 1];
__device__ int   g_wp  [N_NODES];
__device__ int   g_src_s[N_EDGES];
__device__ float g_w_s [N_EDGES];
__device__ __align__(16) float g_y1[N_NODES * HID_C];   // x @ W_l1^T
__device__ __align__(16) float g_r1[N_NODES * HID_C];   // x @ W_r1^T
__device__ __align__(16) float g_h [N_NODES * HID_C];   // layer-1 output
__device__ __align__(16) float g_y2[N_NODES * OUT_C];   // h @ W_l2^T
__device__ __align__(16) float g_r2[N_NODES * OUT_C];   // h @ W_r2^T

// ---------------- CSR build -------------------------------------------------------
__global__ void zero_cnt_kernel() {
    int i = blockIdx.x * blockDim.x + threadIdx.x;
    if (i < N_NODES) g_cnt[i] = 0;
}

__global__ void hist_kernel(const int* __restrict__ dst) {
    int e = blockIdx.x * blockDim.x + threadIdx.x;
    if (e < N_EDGES) atomicAdd(&g_cnt[dst[e]], 1);
}

// per-block exclusive scan of counts; per-block totals into g_bsum
__global__ void scanA_kernel() {
    __shared__ int sh[256];
    int t = threadIdx.x;
    int i = blockIdx.x * 256 + t;
    int v = (i < N_NODES) ? g_cnt[i] : 0;
    sh[t] = v;
    __syncthreads();
#pragma unroll
    for (int off = 1; off < 256; off <<= 1) {
        int add = (t >= off) ? sh[t - off] : 0;
        __syncthreads();
        sh[t] += add;
        __syncthreads();
    }
    int incl = sh[t];
    if (i < N_NODES) g_pre[i] = incl - v;
    if (t == 255) g_bsum[blockIdx.x] = incl;
}

// scan of the (<=256) block sums
__global__ void scanB_kernel() {
    __shared__ int sh[256];
    int t = threadIdx.x;
    int v = (t < SCAN_BLOCKS) ? g_bsum[t] : 0;
    sh[t] = v;
    __syncthreads();
#pragma unroll
    for (int off = 1; off < 256; off <<= 1) {
        int add = (t >= off) ? sh[t - off] : 0;
        __syncthreads();
        sh[t] += add;
        __syncthreads();
    }
    g_boff[t] = sh[t] - v;   // exclusive
}

__global__ void scanC_kernel() {
    int i = blockIdx.x * 256 + threadIdx.x;
    if (i < N_NODES) {
        int rp = g_pre[i] + g_boff[blockIdx.x];
        g_rowptr[i] = rp;
        g_wp[i] = rp;
    }
    if (blockIdx.x == 0 && threadIdx.x == 0) g_rowptr[N_NODES] = N_EDGES;
}

__global__ void scatter_kernel(const int* __restrict__ src,
                               const int* __restrict__ dst,
                               const float* __restrict__ ew) {
    int e = blockIdx.x * blockDim.x + threadIdx.x;
    if (e >= N_EDGES) return;
    int pos = atomicAdd(&g_wp[dst[e]], 1);
    g_src_s[pos] = src[e];
    g_w_s[pos]   = ew[e];
}

// ---------------- gather aggregation + fused SAGE epilogue ------------------------
// out[node] = [relu]( mean_e(w_e * y[src_e]) + bias + r[node] )
// C=128: one warp per node, each lane owns a float4.
template <bool RELU>
__global__ void __launch_bounds__(256)
gather128_kernel(const float* __restrict__ y, const float* __restrict__ r,
                 const float* __restrict__ bias, float* __restrict__ out) {
    int gt = blockIdx.x * blockDim.x + threadIdx.x;
    int node = gt >> 5;
    if (node >= N_NODES) return;
    int lane = threadIdx.x & 31;

    int beg = g_rowptr[node];
    int end = g_rowptr[node + 1];

    float ax = 0.f, ay = 0.f, az = 0.f, aw = 0.f;
    int i = beg;
    for (; i + 4 <= end; i += 4) {
        int   s0 = g_src_s[i],   s1 = g_src_s[i+1], s2 = g_src_s[i+2], s3 = g_src_s[i+3];
        float w0 = g_w_s[i],     w1 = g_w_s[i+1],   w2 = g_w_s[i+2],   w3 = g_w_s[i+3];
        float4 v0 = *reinterpret_cast<const float4*>(y + (size_t)s0 * 128 + lane * 4);
        float4 v1 = *reinterpret_cast<const float4*>(y + (size_t)s1 * 128 + lane * 4);
        float4 v2 = *reinterpret_cast<const float4*>(y + (size_t)s2 * 128 + lane * 4);
        float4 v3 = *reinterpret_cast<const float4*>(y + (size_t)s3 * 128 + lane * 4);
        ax += w0*v0.x + w1*v1.x + w2*v2.x + w3*v3.x;
        ay += w0*v0.y + w1*v1.y + w2*v2.y + w3*v3.y;
        az += w0*v0.z + w1*v1.z + w2*v2.z + w3*v3.z;
        aw += w0*v0.w + w1*v1.w + w2*v2.w + w3*v3.w;
    }
    for (; i < end; i++) {
        int s = g_src_s[i];
        float w = g_w_s[i];
        float4 v = *reinterpret_cast<const float4*>(y + (size_t)s * 128 + lane * 4);
        ax += w*v.x; ay += w*v.y; az += w*v.z; aw += w*v.w;
    }

    float invd = 1.0f / fmaxf((float)(end - beg), 1.0f);
    float4 r4 = *reinterpret_cast<const float4*>(r + (size_t)node * 128 + lane * 4);
    float4 b4 = *reinterpret_cast<const float4*>(bias + lane * 4);
    float4 o;
    o.x = ax * invd + b4.x + r4.x;
    o.y = ay * invd + b4.y + r4.y;
    o.z = az * invd + b4.z + r4.z;
    o.w = aw * invd + b4.w + r4.w;
    if (RELU) {
        o.x = fmaxf(o.x, 0.f); o.y = fmaxf(o.y, 0.f);
        o.z = fmaxf(o.z, 0.f); o.w = fmaxf(o.w, 0.f);
    }
    *reinterpret_cast<float4*>(out + (size_t)node * 128 + lane * 4) = o;
}

// C=64: one half-warp (16 threads) per node, each lane owns a float4.
template <bool RELU>
__global__ void __launch_bounds__(256)
gather64_kernel(const float* __restrict__ y, const float* __restrict__ r,
                const float* __restrict__ bias, float* __restrict__ out) {
    int gt = blockIdx.x * blockDim.x + threadIdx.x;
    int node = gt >> 4;
    if (node >= N_NODES) return;
    int lane = threadIdx.x & 15;

    int beg = g_rowptr[node];
    int end = g_rowptr[node + 1];

    float ax = 0.f, ay = 0.f, az = 0.f, aw = 0.f;
    int i = beg;
    for (; i + 4 <= end; i += 4) {
        int   s0 = g_src_s[i],   s1 = g_src_s[i+1], s2 = g_src_s[i+2], s3 = g_src_s[i+3];
        float w0 = g_w_s[i],     w1 = g_w_s[i+1],   w2 = g_w_s[i+2],   w3 = g_w_s[i+3];
        float4 v0 = *reinterpret_cast<const float4*>(y + (size_t)s0 * 64 + lane * 4);
        float4 v1 = *reinterpret_cast<const float4*>(y + (size_t)s1 * 64 + lane * 4);
        float4 v2 = *reinterpret_cast<const float4*>(y + (size_t)s2 * 64 + lane * 4);
        float4 v3 = *reinterpret_cast<const float4*>(y + (size_t)s3 * 64 + lane * 4);
        ax += w0*v0.x + w1*v1.x + w2*v2.x + w3*v3.x;
        ay += w0*v0.y + w1*v1.y + w2*v2.y + w3*v3.y;
        az += w0*v0.z + w1*v1.z + w2*v2.z + w3*v3.z;
        aw += w0*v0.w + w1*v1.w + w2*v2.w + w3*v3.w;
    }
    for (; i < end; i++) {
        int s = g_src_s[i];
        float w = g_w_s[i];
        float4 v = *reinterpret_cast<const float4*>(y + (size_t)s * 64 + lane * 4);
        ax += w*v.x; ay += w*v.y; az += w*v.z; aw += w*v.w;
    }

    float invd = 1.0f / fmaxf((float)(end - beg), 1.0f);
    float4 r4 = *reinterpret_cast<const float4*>(r + (size_t)node * 64 + lane * 4);
    float4 b4 = *reinterpret_cast<const float4*>(bias + lane * 4);
    float4 o;
    o.x = ax * invd + b4.x + r4.x;
    o.y = ay * invd + b4.y + r4.y;
    o.z = az * invd + b4.z + r4.z;
    o.w = aw * invd + b4.w + r4.w;
    if (RELU) {
        o.x = fmaxf(o.x, 0.f); o.y = fmaxf(o.y, 0.f);
        o.z = fmaxf(o.z, 0.f); o.w = fmaxf(o.w, 0.f);
    }
    *reinterpret_cast<float4*>(out + (size_t)node * 64 + lane * 4) = o;
}

// ---------------- dual GEMM: out{0,1} = A @ W{0,1}^T (blockIdx.y selects) --------
// A: [n,128] row-major, W: [BN,128] row-major. BM=64, KC=32.
template <int BN>
__global__ void __launch_bounds__(256)
gemm2_kernel(const float* __restrict__ A,
             const float* __restrict__ W0, const float* __restrict__ W1,
             float* __restrict__ out0, float* __restrict__ out1, int n) {
    constexpr int BM = 64, K = 128, KC = 32;
    constexpr int TN = BN / 16;
    const float* W   = blockIdx.y ? W1 : W0;
    float*       out = blockIdx.y ? out1 : out0;

    __shared__ float As[KC][68];
    __shared__ float Ws[KC][BN + 4];

    int row0 = blockIdx.x * BM;
    int tid = threadIdx.x;
    int tr = tid >> 4;
    int tc = tid & 15;

    float acc[4][TN];
#pragma unroll
    for (int i = 0; i < 4; i++)
#pragma unroll
        for (int j = 0; j < TN; j++) acc[i][j] = 0.f;

    for (int kc = 0; kc < K; kc += KC) {
#pragma unroll
        for (int it = 0; it < 2; it++) {
            int idx = tid + it * 256;
            int row = idx >> 3;
            int k4  = idx & 7;
            float4 v = make_float4(0.f, 0.f, 0.f, 0.f);
            if (row0 + row < n)
                v = *reinterpret_cast<const float4*>(A + (size_t)(row0 + row) * K + kc + k4 * 4);
            As[k4 * 4 + 0][row] = v.x;
            As[k4 * 4 + 1][row] = v.y;
            As[k4 * 4 + 2][row] = v.z;
            As[k4 * 4 + 3][row] = v.w;
        }
#pragma unroll
        for (int it = 0; it < BN * 8 / 256; it++) {
            int idx = tid + it * 256;
            int c  = idx >> 3;
            int k4 = idx & 7;
            float4 v = *reinterpret_cast<const float4*>(W + (size_t)c * K + kc + k4 * 4);
            Ws[k4 * 4 + 0][c] = v.x;
            Ws[k4 * 4 + 1][c] = v.y;
            Ws[k4 * 4 + 2][c] = v.z;
            Ws[k4 * 4 + 3][c] = v.w;
        }
        __syncthreads();
#pragma unroll
        for (int k = 0; k < KC; k++) {
            float4 a = *reinterpret_cast<const float4*>(&As[k][tr * 4]);
            float av[4] = {a.x, a.y, a.z, a.w};
            float bv[TN];
#pragma unroll
            for (int j0 = 0; j0 < TN; j0 += 4) {
                float4 b = *reinterpret_cast<const float4*>(&Ws[k][tc * TN + j0]);
                bv[j0 + 0] = b.x; bv[j0 + 1] = b.y; bv[j0 + 2] = b.z; bv[j0 + 3] = b.w;
            }
#pragma unroll
            for (int i = 0; i < 4; i++)
#pragma unroll
                for (int j = 0; j < TN; j++)
                    acc[i][j] = fmaf(av[i], bv[j], acc[i][j]);
        }
        __syncthreads();
    }

#pragma unroll
    for (int i = 0; i < 4; i++) {
        int r = row0 + tr * 4 + i;
        if (r >= n) continue;
#pragma unroll
        for (int j = 0; j < TN; j++)
            out[(size_t)r * BN + tc * TN + j] = acc[i][j];
    }
}

// ---------------- launch ----------------------------------------------------------
extern "C" void kernel_launch(void* const* d_in, const int* in_sizes, int n_in,
                              void* d_out, int out_size) {
    const float* x    = (const float*)d_in[0];
    const int*   ei   = (const int*)  d_in[1];
    const float* ew   = (const float*)d_in[2];
    // d_in[3] = node_type (unused by the reference)
    const float* W_l1 = (const float*)d_in[4];
    const float* b_l1 = (const float*)d_in[5];
    const float* W_r1 = (const float*)d_in[6];
    const float* W_l2 = (const float*)d_in[7];
    const float* b_l2 = (const float*)d_in[8];
    const float* W_r2 = (const float*)d_in[9];
    float* out = (float*)d_out;

    const int* src = ei;
    const int* dst = ei + N_EDGES;

    float *y1, *r1, *h, *y2, *r2;
    cudaGetSymbolAddress((void**)&y1, g_y1);
    cudaGetSymbolAddress((void**)&r1, g_r1);
    cudaGetSymbolAddress((void**)&h,  g_h);
    cudaGetSymbolAddress((void**)&y2, g_y2);
    cudaGetSymbolAddress((void**)&r2, g_r2);

    const int EB = (N_EDGES + 255) / 256;   // 3125

    // --- CSR build (dst-sorted) ---
    zero_cnt_kernel<<<SCAN_BLOCKS, 256>>>();
    hist_kernel<<<EB, 256>>>(dst);
    scanA_kernel<<<SCAN_BLOCKS, 256>>>();
    scanB_kernel<<<1, 256>>>();
    scanC_kernel<<<SCAN_BLOCKS, 256>>>();
    scatter_kernel<<<EB, 256>>>(src, dst, ew);

    // --- layer 1: project first (linearity), gather-mean, fused epilogue ---
    gemm2_kernel<128><<<dim3((N_NODES + 63) / 64, 2), 256>>>(x, W_l1, W_r1, y1, r1, N_NODES);
    gather128_kernel<true><<<(N_NODES * 32 + 255) / 256, 256>>>(y1, r1, b_l1, h);

    // --- layer 2: project to 64 dims before aggregating ---
    gemm2_kernel<64><<<dim3((N_NODES + 63) / 64, 2), 256>>>(h, W_l2, W_r2, y2, r2, N_NODES);
    gather64_kernel<false><<<(N_NODES * 16 + 255) / 256, 256>>>(y2, r2, b_l2, out);
}

// round 3
// speedup vs baseline: 1.5354x; 1.1337x over previous
#include <cuda_runtime.h>
#include <cstddef>
#include <cstring>

#define N_NODES 50000
#define N_EDGES 800000
#define IN_C 128
#define HID_C 128
#define OUT_C 64

// ---------------- scratch (device globals: allocation-free rule) ----------------
__device__ int   g_cnt [N_NODES];
__device__ int   g_rowptr[N_NODES + 1];
__device__ int   g_wp  [N_NODES];
__device__ int   g_src_s[N_EDGES];
__device__ float g_w_s [N_EDGES];
__device__ __align__(16) float g_y1[N_NODES * HID_C];   // x @ W_l1^T
__device__ __align__(16) float g_r1[N_NODES * HID_C];   // x @ W_r1^T
__device__ __align__(16) float g_h [N_NODES * HID_C];   // layer-1 output
__device__ __align__(16) float g_y2[N_NODES * OUT_C];   // h @ W_l2^T
__device__ __align__(16) float g_r2[N_NODES * OUT_C];   // h @ W_r2^T

// ---------------- CSR build -------------------------------------------------------
__global__ void zero_cnt_kernel() {
    int i = blockIdx.x * blockDim.x + threadIdx.x;
    if (i < N_NODES) g_cnt[i] = 0;
}

__global__ void hist_kernel(const int* __restrict__ dst) {
    int e = blockIdx.x * blockDim.x + threadIdx.x;
    if (e < N_EDGES) atomicAdd(&g_cnt[dst[e]], 1);
}

// single-block exclusive scan over all N_NODES counts -> rowptr, wp
__global__ void __launch_bounds__(1024) scan_kernel() {
    __shared__ int wsum[32];
    int t = threadIdx.x;
    int lane = t & 31;
    int wid = t >> 5;
    int carry = 0;

    for (int base = 0; base < N_NODES; base += 4096) {
        int i0 = base + t * 4;
        int4 c = make_int4(0, 0, 0, 0);
        if (i0 < N_NODES)                                   // N_NODES % 4 == 0
            c = *reinterpret_cast<const int4*>(&g_cnt[i0]);
        int s0 = c.x, s1 = s0 + c.y, s2 = s1 + c.z, s3 = s2 + c.w;
        int tot = s3;

        // warp inclusive scan of per-thread totals
        int inc = tot;
#pragma unroll
        for (int off = 1; off < 32; off <<= 1) {
            int v = __shfl_up_sync(0xffffffffu, inc, off);
            if (lane >= off) inc += v;
        }
        if (lane == 31) wsum[wid] = inc;
        __syncthreads();
        if (wid == 0) {
            int v = wsum[lane];
            int iv = v;
#pragma unroll
            for (int off = 1; off < 32; off <<= 1) {
                int u = __shfl_up_sync(0xffffffffu, iv, off);
                if (lane >= off) iv += u;
            }
            wsum[lane] = iv;
        }
        __syncthreads();
        int woff = (wid > 0) ? wsum[wid - 1] : 0;
        int ex = carry + woff + inc - tot;   // exclusive prefix of this thread's first elem

        if (i0 < N_NODES) {
            g_rowptr[i0 + 0] = ex;          g_wp[i0 + 0] = ex;
            g_rowptr[i0 + 1] = ex + s0;     g_wp[i0 + 1] = ex + s0;
            g_rowptr[i0 + 2] = ex + s1;     g_wp[i0 + 2] = ex + s1;
            g_rowptr[i0 + 3] = ex + s2;     g_wp[i0 + 3] = ex + s2;
        }
        carry += wsum[31];
        __syncthreads();
    }
    if (t == 0) g_rowptr[N_NODES] = N_EDGES;
}

__global__ void scatter_kernel(const int* __restrict__ src,
                               const int* __restrict__ dst,
                               const float* __restrict__ ew) {
    int e = blockIdx.x * blockDim.x + threadIdx.x;
    if (e >= N_EDGES) return;
    int pos = atomicAdd(&g_wp[dst[e]], 1);
    g_src_s[pos] = src[e];
    g_w_s[pos]   = ew[e];
}

// ---------------- gather aggregation + fused SAGE epilogue ------------------------
template <bool RELU>
__global__ void __launch_bounds__(256)
gather128_kernel(const float* __restrict__ y, const float* __restrict__ r,
                 const float* __restrict__ bias, float* __restrict__ out) {
    int gt = blockIdx.x * blockDim.x + threadIdx.x;
    int node = gt >> 5;
    if (node >= N_NODES) return;
    int lane = threadIdx.x & 31;

    int beg = g_rowptr[node];
    int end = g_rowptr[node + 1];

    float ax = 0.f, ay = 0.f, az = 0.f, aw = 0.f;
    int i = beg;
    for (; i + 4 <= end; i += 4) {
        int   s0 = g_src_s[i],   s1 = g_src_s[i+1], s2 = g_src_s[i+2], s3 = g_src_s[i+3];
        float w0 = g_w_s[i],     w1 = g_w_s[i+1],   w2 = g_w_s[i+2],   w3 = g_w_s[i+3];
        float4 v0 = *reinterpret_cast<const float4*>(y + (size_t)s0 * 128 + lane * 4);
        float4 v1 = *reinterpret_cast<const float4*>(y + (size_t)s1 * 128 + lane * 4);
        float4 v2 = *reinterpret_cast<const float4*>(y + (size_t)s2 * 128 + lane * 4);
        float4 v3 = *reinterpret_cast<const float4*>(y + (size_t)s3 * 128 + lane * 4);
        ax += w0*v0.x + w1*v1.x + w2*v2.x + w3*v3.x;
        ay += w0*v0.y + w1*v1.y + w2*v2.y + w3*v3.y;
        az += w0*v0.z + w1*v1.z + w2*v2.z + w3*v3.z;
        aw += w0*v0.w + w1*v1.w + w2*v2.w + w3*v3.w;
    }
    for (; i < end; i++) {
        int s = g_src_s[i];
        float w = g_w_s[i];
        float4 v = *reinterpret_cast<const float4*>(y + (size_t)s * 128 + lane * 4);
        ax += w*v.x; ay += w*v.y; az += w*v.z; aw += w*v.w;
    }

    float invd = 1.0f / fmaxf((float)(end - beg), 1.0f);
    float4 r4 = *reinterpret_cast<const float4*>(r + (size_t)node * 128 + lane * 4);
    float4 b4 = *reinterpret_cast<const float4*>(bias + lane * 4);
    float4 o;
    o.x = ax * invd + b4.x + r4.x;
    o.y = ay * invd + b4.y + r4.y;
    o.z = az * invd + b4.z + r4.z;
    o.w = aw * invd + b4.w + r4.w;
    if (RELU) {
        o.x = fmaxf(o.x, 0.f); o.y = fmaxf(o.y, 0.f);
        o.z = fmaxf(o.z, 0.f); o.w = fmaxf(o.w, 0.f);
    }
    *reinterpret_cast<float4*>(out + (size_t)node * 128 + lane * 4) = o;
}

template <bool RELU>
__global__ void __launch_bounds__(256)
gather64_kernel(const float* __restrict__ y, const float* __restrict__ r,
                const float* __restrict__ bias, float* __restrict__ out) {
    int gt = blockIdx.x * blockDim.x + threadIdx.x;
    int node = gt >> 4;
    if (node >= N_NODES) return;
    int lane = threadIdx.x & 15;

    int beg = g_rowptr[node];
    int end = g_rowptr[node + 1];

    float ax = 0.f, ay = 0.f, az = 0.f, aw = 0.f;
    int i = beg;
    for (; i + 4 <= end; i += 4) {
        int   s0 = g_src_s[i],   s1 = g_src_s[i+1], s2 = g_src_s[i+2], s3 = g_src_s[i+3];
        float w0 = g_w_s[i],     w1 = g_w_s[i+1],   w2 = g_w_s[i+2],   w3 = g_w_s[i+3];
        float4 v0 = *reinterpret_cast<const float4*>(y + (size_t)s0 * 64 + lane * 4);
        float4 v1 = *reinterpret_cast<const float4*>(y + (size_t)s1 * 64 + lane * 4);
        float4 v2 = *reinterpret_cast<const float4*>(y + (size_t)s2 * 64 + lane * 4);
        float4 v3 = *reinterpret_cast<const float4*>(y + (size_t)s3 * 64 + lane * 4);
        ax += w0*v0.x + w1*v1.x + w2*v2.x + w3*v3.x;
        ay += w0*v0.y + w1*v1.y + w2*v2.y + w3*v3.y;
        az += w0*v0.z + w1*v1.z + w2*v2.z + w3*v3.z;
        aw += w0*v0.w + w1*v1.w + w2*v2.w + w3*v3.w;
    }
    for (; i < end; i++) {
        int s = g_src_s[i];
        float w = g_w_s[i];
        float4 v = *reinterpret_cast<const float4*>(y + (size_t)s * 64 + lane * 4);
        ax += w*v.x; ay += w*v.y; az += w*v.z; aw += w*v.w;
    }

    float invd = 1.0f / fmaxf((float)(end - beg), 1.0f);
    float4 r4 = *reinterpret_cast<const float4*>(r + (size_t)node * 64 + lane * 4);
    float4 b4 = *reinterpret_cast<const float4*>(bias + lane * 4);
    float4 o;
    o.x = ax * invd + b4.x + r4.x;
    o.y = ay * invd + b4.y + r4.y;
    o.z = az * invd + b4.z + r4.z;
    o.w = aw * invd + b4.w + r4.w;
    if (RELU) {
        o.x = fmaxf(o.x, 0.f); o.y = fmaxf(o.y, 0.f);
        o.z = fmaxf(o.z, 0.f); o.w = fmaxf(o.w, 0.f);
    }
    *reinterpret_cast<float4*>(out + (size_t)node * 64 + lane * 4) = o;
}

// ---------------- f32x2 packed-FMA GEMM -------------------------------------------
// Virtual weight matrix = [W0; W1] stacked ([split + split] x 128).
// out0[r, vc] for vc < split, out1[r, vc-split] otherwise; both strides = split.
// BM=128 rows x 128 virtual cols per block (col base = blockIdx.y * 128).
// 256 threads, 8x8 per thread as 8 x 4 f32x2 accumulators.

#define FMA2(d, a, b) asm("fma.rn.f32x2 %0, %1, %2, %0;" : "+l"(d) : "l"(a), "l"(b))

typedef unsigned long long u64;

__device__ __forceinline__ float2 u64_as_f2(u64 v) {
    float2 f;
    memcpy(&f, &v, 8);
    return f;
}

__global__ void __launch_bounds__(256)
gemm2x_kernel(const float* __restrict__ A,
              const float* __restrict__ W0, const float* __restrict__ W1,
              float* __restrict__ out0, float* __restrict__ out1,
              int split, int n) {
    constexpr int BM = 128, K = 128, KC = 16;
    constexpr int APAD = 2 * BM + 4;   // 260 floats per k-row (duplicated A)
    constexpr int WPAD = 128 + 4;      // 132 floats per k-row

    __shared__ float As[KC][APAD];     // As[k][2m] = As[k][2m+1] = A[row0+m][k]
    __shared__ float Ws[KC][WPAD];     // Ws[k][c]  = Wvirt[col0+c][k]

    int row0 = blockIdx.x * BM;
    int col0 = blockIdx.y * 128;
    int tid = threadIdx.x;
    int tx = tid & 15;                 // column group
    int ty = tid >> 4;                 // row group (8 rows)

    u64 acc[8][4];
#pragma unroll
    for (int i = 0; i < 8; i++)
#pragma unroll
        for (int j = 0; j < 4; j++) acc[i][j] = 0ull;

    for (int kc = 0; kc < K; kc += KC) {
        // ---- load A chunk: 128 rows x 16 k, duplicated along columns ----
#pragma unroll
        for (int it = 0; it < 2; it++) {
            int idx = tid + it * 256;          // 0..511
            int row = idx >> 2;
            int k4  = idx & 3;
            float4 v = make_float4(0.f, 0.f, 0.f, 0.f);
            if (row0 + row < n)
                v = *reinterpret_cast<const float4*>(A + (size_t)(row0 + row) * K + kc + k4 * 4);
            float2* dst0 = reinterpret_cast<float2*>(&As[k4 * 4 + 0][2 * row]);
            float2* dst1 = reinterpret_cast<float2*>(&As[k4 * 4 + 1][2 * row]);
            float2* dst2 = reinterpret_cast<float2*>(&As[k4 * 4 + 2][2 * row]);
            float2* dst3 = reinterpret_cast<float2*>(&As[k4 * 4 + 3][2 * row]);
            *dst0 = make_float2(v.x, v.x);
            *dst1 = make_float2(v.y, v.y);
            *dst2 = make_float2(v.z, v.z);
            *dst3 = make_float2(v.w, v.w);
        }
        // ---- load W chunk: 128 virtual cols x 16 k ----
#pragma unroll
        for (int it = 0; it < 2; it++) {
            int idx = tid + it * 256;
            int c   = idx >> 2;
            int k4  = idx & 3;
            int vc  = col0 + c;
            const float* wrow = (vc < split) ? (W0 + (size_t)vc * K)
                                             : (W1 + (size_t)(vc - split) * K);
            float4 v = *reinterpret_cast<const float4*>(wrow + kc + k4 * 4);
            Ws[k4 * 4 + 0][c] = v.x;
            Ws[k4 * 4 + 1][c] = v.y;
            Ws[k4 * 4 + 2][c] = v.z;
            Ws[k4 * 4 + 3][c] = v.w;
        }
        __syncthreads();

        // ---- compute ----
#pragma unroll
        for (int k = 0; k < KC; k++) {
            // a: 8 duplicated pairs (rows ty*8 .. ty*8+7)
            const ulonglong2* au = reinterpret_cast<const ulonglong2*>(&As[k][16 * ty]);
            ulonglong2 a01 = au[0];
            ulonglong2 a23 = au[1];
            ulonglong2 a45 = au[2];
            ulonglong2 a67 = au[3];
            u64 ad[8] = {a01.x, a01.y, a23.x, a23.y, a45.x, a45.y, a67.x, a67.y};
            // b: 4 natural pairs (cols 4tx..4tx+3 and 64+4tx..64+4tx+3)
            ulonglong2 b01 = *reinterpret_cast<const ulonglong2*>(&Ws[k][4 * tx]);
            ulonglong2 b23 = *reinterpret_cast<const ulonglong2*>(&Ws[k][64 + 4 * tx]);
            u64 bp[4] = {b01.x, b01.y, b23.x, b23.y};
#pragma unroll
            for (int i = 0; i < 8; i++) {
                FMA2(acc[i][0], ad[i], bp[0]);
                FMA2(acc[i][1], ad[i], bp[1]);
                FMA2(acc[i][2], ad[i], bp[2]);
                FMA2(acc[i][3], ad[i], bp[3]);
            }
        }
        __syncthreads();
    }

    // ---- writeback: two float4 groups per row ----
    int vcA = col0 + 4 * tx;           // group A: 4 cols
    int vcB = col0 + 64 + 4 * tx;      // group B: 4 cols
    float* baseA = (vcA < split) ? (out0 + vcA) : (out1 + (vcA - split));
    float* baseB = (vcB < split) ? (out0 + vcB) : (out1 + (vcB - split));
#pragma unroll
    for (int i = 0; i < 8; i++) {
        int r = row0 + ty * 8 + i;
        if (r >= n) continue;
        float2 a0 = u64_as_f2(acc[i][0]);
        float2 a1 = u64_as_f2(acc[i][1]);
        float2 b0 = u64_as_f2(acc[i][2]);
        float2 b1 = u64_as_f2(acc[i][3]);
        *reinterpret_cast<float4*>(baseA + (size_t)r * split) = make_float4(a0.x, a0.y, a1.x, a1.y);
        *reinterpret_cast<float4*>(baseB + (size_t)r * split) = make_float4(b0.x, b0.y, b1.x, b1.y);
    }
}

// ---------------- launch ----------------------------------------------------------
extern "C" void kernel_launch(void* const* d_in, const int* in_sizes, int n_in,
                              void* d_out, int out_size) {
    const float* x    = (const float*)d_in[0];
    const int*   ei   = (const int*)  d_in[1];
    const float* ew   = (const float*)d_in[2];
    // d_in[3] = node_type (unused by the reference)
    const float* W_l1 = (const float*)d_in[4];
    const float* b_l1 = (const float*)d_in[5];
    const float* W_r1 = (const float*)d_in[6];
    const float* W_l2 = (const float*)d_in[7];
    const float* b_l2 = (const float*)d_in[8];
    const float* W_r2 = (const float*)d_in[9];
    float* out = (float*)d_out;

    const int* src = ei;
    const int* dst = ei + N_EDGES;

    float *y1, *r1, *h, *y2, *r2;
    cudaGetSymbolAddress((void**)&y1, g_y1);
    cudaGetSymbolAddress((void**)&r1, g_r1);
    cudaGetSymbolAddress((void**)&h,  g_h);
    cudaGetSymbolAddress((void**)&y2, g_y2);
    cudaGetSymbolAddress((void**)&r2, g_r2);

    const int EB = (N_EDGES + 255) / 256;           // 3125
    const int GB = (N_NODES + 127) / 128;           // 391

    // --- CSR build (dst-sorted): 4 launches ---
    zero_cnt_kernel<<<(N_NODES + 255) / 256, 256>>>();
    hist_kernel<<<EB, 256>>>(dst);
    scan_kernel<<<1, 1024>>>();
    scatter_kernel<<<EB, 256>>>(src, dst, ew);

    // --- layer 1: [W_l1; W_r1] stacked GEMM, gather-mean + fused epilogue ---
    gemm2x_kernel<<<dim3(GB, 2), 256>>>(x, W_l1, W_r1, y1, r1, 128, N_NODES);
    gather128_kernel<true><<<(N_NODES * 32 + 255) / 256, 256>>>(y1, r1, b_l1, h);

    // --- layer 2: [W_l2; W_r2] stacked GEMM (project to 64 before aggregating) ---
    gemm2x_kernel<<<dim3(GB, 1), 256>>>(h, W_l2, W_r2, y2, r2, 64, N_NODES);
    gather64_kernel<false><<<(N_NODES * 16 + 255) / 256, 256>>>(y2, r2, b_l2, out);
}

// round 4
// speedup vs baseline: 1.8508x; 1.2054x over previous
#include <cuda_runtime.h>
#include <cstddef>
#include <cstring>

#define N_NODES 50000
#define N_EDGES 800000
#define IN_C 128
#define HID_C 128
#define OUT_C 64
#define CSR_BLOCKS 148
#define CSR_THREADS 1024
#define CSR_CHUNK 338          // 148*338 = 50024 >= N_NODES

typedef unsigned long long u64;

// ---------------- scratch (device globals: allocation-free rule) ----------------
__device__ int      g_cnt [N_NODES];
__device__ int      g_btot[CSR_BLOCKS];
__device__ int      g_rowptr[N_NODES + 1];
__device__ int      g_wp  [N_NODES];
__device__ u64      g_edge[N_EDGES];                    // packed (src, w)
__device__ unsigned g_bar;                              // monotonic grid-barrier ticket
__device__ __align__(16) float g_y1[N_NODES * HID_C];   // x @ W_l1^T
__device__ __align__(16) float g_r1[N_NODES * HID_C];   // x @ W_r1^T
__device__ __align__(16) float g_h [N_NODES * HID_C];   // layer-1 output
__device__ __align__(16) float g_y2[N_NODES * OUT_C];   // h @ W_l2^T
__device__ __align__(16) float g_r2[N_NODES * OUT_C];   // h @ W_r2^T

// ---------------- grid barrier (monotonic ticket: replay-safe, no reset) ---------
__device__ __forceinline__ void grid_bar() {
    __shared__ unsigned target;
    __syncthreads();
    if (threadIdx.x == 0) {
        __threadfence();
        unsigned t = atomicAdd(&g_bar, 1u);
        target = (t / CSR_BLOCKS + 1u) * CSR_BLOCKS;
        while (atomicAdd(&g_bar, 0u) < target) { }
        __threadfence();
    }
    __syncthreads();
}

// ---------------- single-launch CSR build (zero + hist + scan + scatter) ---------
__global__ void __launch_bounds__(CSR_THREADS)
csr_kernel(const int* __restrict__ src, const int* __restrict__ dst,
           const float* __restrict__ ew) {
    const int t = threadIdx.x;
    const int b = blockIdx.x;
    const int gt = b * CSR_THREADS + t;
    const int G = CSR_BLOCKS * CSR_THREADS;
    const int lane = t & 31;
    const int wid = t >> 5;
    __shared__ int wsum[32];
    __shared__ int s_boff;

    // --- phase 0: zero counts ---
    for (int i = gt; i < N_NODES; i += G) g_cnt[i] = 0;
    grid_bar();

    // --- phase 1: histogram of dst ---
    for (int e = gt; e < N_EDGES; e += G) atomicAdd(&g_cnt[dst[e]], 1);
    grid_bar();

    // --- phase 2: scan. block b owns nodes [b*CSR_CHUNK, ...) ---
    const int base = b * CSR_CHUNK;
    const int node = base + t;
    int v = 0;
    if (t < CSR_CHUNK && node < N_NODES) v = __ldcg(&g_cnt[node]);

    // block-wide inclusive scan over 1024 lanes
    int inc = v;
#pragma unroll
    for (int off = 1; off < 32; off <<= 1) {
        int u = __shfl_up_sync(0xffffffffu, inc, off);
        if (lane >= off) inc += u;
    }
    if (lane == 31) wsum[wid] = inc;
    __syncthreads();
    if (wid == 0) {
        int wv = wsum[lane];
        int wi = wv;
#pragma unroll
        for (int off = 1; off < 32; off <<= 1) {
            int u = __shfl_up_sync(0xffffffffu, wi, off);
            if (lane >= off) wi += u;
        }
        wsum[lane] = wi;
    }
    __syncthreads();
    int ex = inc - v + ((wid > 0) ? wsum[wid - 1] : 0);  // exclusive within block
    int btot = wsum[31];
    if (t == 0) g_btot[b] = btot;
    __threadfence();
    grid_bar();

    // block offset = sum of btot[0..b-1]  (block-wide reduction of masked loads)
    {
        int contrib = (t < b) ? __ldcg(&g_btot[t]) : 0;
        int r = contrib;
#pragma unroll
        for (int off = 16; off > 0; off >>= 1) r += __shfl_down_sync(0xffffffffu, r, off);
        if (lane == 0) wsum[wid] = r;
        __syncthreads();
        if (wid == 0) {
            int r2 = wsum[lane];
#pragma unroll
            for (int off = 16; off > 0; off >>= 1) r2 += __shfl_down_sync(0xffffffffu, r2, off);
            if (lane == 0) s_boff = r2;
        }
        __syncthreads();
    }
    if (t < CSR_CHUNK && node < N_NODES) {
        int rp = s_boff + ex;
        g_rowptr[node] = rp;
        g_wp[node] = rp;
    }
    if (b == 0 && t == 0) g_rowptr[N_NODES] = N_EDGES;
    __threadfence();
    grid_bar();

    // --- phase 3: scatter packed (src, w) records ---
    for (int e = gt; e < N_EDGES; e += G) {
        int d = dst[e];
        int pos = atomicAdd(&g_wp[d], 1);
        u64 rec = ((u64)__float_as_uint(ew[e]) << 32) | (unsigned)src[e];
        g_edge[pos] = rec;
    }
}

// ---------------- gather aggregation + fused SAGE epilogue ------------------------
__device__ __forceinline__ void unpack_edge(u64 rec, int& s, float& w) {
    s = (int)(unsigned)rec;
    w = __uint_as_float((unsigned)(rec >> 32));
}

template <bool RELU>
__global__ void __launch_bounds__(256)
gather128_kernel(const float* __restrict__ y, const float* __restrict__ r,
                 const float* __restrict__ bias, float* __restrict__ out) {
    int gt = blockIdx.x * blockDim.x + threadIdx.x;
    int node = gt >> 5;
    if (node >= N_NODES) return;
    int lane = threadIdx.x & 31;

    int beg = g_rowptr[node];
    int end = g_rowptr[node + 1];

    float ax = 0.f, ay = 0.f, az = 0.f, aw = 0.f;
    int i = beg;
    for (; i + 4 <= end; i += 4) {
        int s0, s1, s2, s3; float w0, w1, w2, w3;
        unpack_edge(g_edge[i],   s0, w0);
        unpack_edge(g_edge[i+1], s1, w1);
        unpack_edge(g_edge[i+2], s2, w2);
        unpack_edge(g_edge[i+3], s3, w3);
        float4 v0 = *reinterpret_cast<const float4*>(y + (size_t)s0 * 128 + lane * 4);
        float4 v1 = *reinterpret_cast<const float4*>(y + (size_t)s1 * 128 + lane * 4);
        float4 v2 = *reinterpret_cast<const float4*>(y + (size_t)s2 * 128 + lane * 4);
        float4 v3 = *reinterpret_cast<const float4*>(y + (size_t)s3 * 128 + lane * 4);
        ax += w0*v0.x + w1*v1.x + w2*v2.x + w3*v3.x;
        ay += w0*v0.y + w1*v1.y + w2*v2.y + w3*v3.y;
        az += w0*v0.z + w1*v1.z + w2*v2.z + w3*v3.z;
        aw += w0*v0.w + w1*v1.w + w2*v2.w + w3*v3.w;
    }
    for (; i < end; i++) {
        int s; float w;
        unpack_edge(g_edge[i], s, w);
        float4 v = *reinterpret_cast<const float4*>(y + (size_t)s * 128 + lane * 4);
        ax += w*v.x; ay += w*v.y; az += w*v.z; aw += w*v.w;
    }

    float invd = 1.0f / fmaxf((float)(end - beg), 1.0f);
    float4 r4 = *reinterpret_cast<const float4*>(r + (size_t)node * 128 + lane * 4);
    float4 b4 = *reinterpret_cast<const float4*>(bias + lane * 4);
    float4 o;
    o.x = ax * invd + b4.x + r4.x;
    o.y = ay * invd + b4.y + r4.y;
    o.z = az * invd + b4.z + r4.z;
    o.w = aw * invd + b4.w + r4.w;
    if (RELU) {
        o.x = fmaxf(o.x, 0.f); o.y = fmaxf(o.y, 0.f);
        o.z = fmaxf(o.z, 0.f); o.w = fmaxf(o.w, 0.f);
    }
    *reinterpret_cast<float4*>(out + (size_t)node * 128 + lane * 4) = o;
}

template <bool RELU>
__global__ void __launch_bounds__(256)
gather64_kernel(const float* __restrict__ y, const float* __restrict__ r,
                const float* __restrict__ bias, float* __restrict__ out) {
    int gt = blockIdx.x * blockDim.x + threadIdx.x;
    int node = gt >> 4;
    if (node >= N_NODES) return;
    int lane = threadIdx.x & 15;

    int beg = g_rowptr[node];
    int end = g_rowptr[node + 1];

    float ax = 0.f, ay = 0.f, az = 0.f, aw = 0.f;
    int i = beg;
    for (; i + 4 <= end; i += 4) {
        int s0, s1, s2, s3; float w0, w1, w2, w3;
        unpack_edge(g_edge[i],   s0, w0);
        unpack_edge(g_edge[i+1], s1, w1);
        unpack_edge(g_edge[i+2], s2, w2);
        unpack_edge(g_edge[i+3], s3, w3);
        float4 v0 = *reinterpret_cast<const float4*>(y + (size_t)s0 * 64 + lane * 4);
        float4 v1 = *reinterpret_cast<const float4*>(y + (size_t)s1 * 64 + lane * 4);
        float4 v2 = *reinterpret_cast<const float4*>(y + (size_t)s2 * 64 + lane * 4);
        float4 v3 = *reinterpret_cast<const float4*>(y + (size_t)s3 * 64 + lane * 4);
        ax += w0*v0.x + w1*v1.x + w2*v2.x + w3*v3.x;
        ay += w0*v0.y + w1*v1.y + w2*v2.y + w3*v3.y;
        az += w0*v0.z + w1*v1.z + w2*v2.z + w3*v3.z;
        aw += w0*v0.w + w1*v1.w + w2*v2.w + w3*v3.w;
    }
    for (; i < end; i++) {
        int s; float w;
        unpack_edge(g_edge[i], s, w);
        float4 v = *reinterpret_cast<const float4*>(y + (size_t)s * 64 + lane * 4);
        ax += w*v.x; ay += w*v.y; az += w*v.z; aw += w*v.w;
    }

    float invd = 1.0f / fmaxf((float)(end - beg), 1.0f);
    float4 r4 = *reinterpret_cast<const float4*>(r + (size_t)node * 64 + lane * 4);
    float4 b4 = *reinterpret_cast<const float4*>(bias + lane * 4);
    float4 o;
    o.x = ax * invd + b4.x + r4.x;
    o.y = ay * invd + b4.y + r4.y;
    o.z = az * invd + b4.z + r4.z;
    o.w = aw * invd + b4.w + r4.w;
    if (RELU) {
        o.x = fmaxf(o.x, 0.f); o.y = fmaxf(o.y, 0.f);
        o.z = fmaxf(o.z, 0.f); o.w = fmaxf(o.w, 0.f);
    }
    *reinterpret_cast<float4*>(out + (size_t)node * 64 + lane * 4) = o;
}

// ---------------- f32x2 packed-FMA GEMM, double-buffered -------------------------
// Virtual weight matrix = [W0; W1] stacked. BM=128 x 128 virtual cols per block.
// 256 threads, 8x8 per thread as 8 x 4 f32x2 accumulators. KC=8, 2 smem buffers.

#define FMA2(d, a, b) asm("fma.rn.f32x2 %0, %1, %2, %0;" : "+l"(d) : "l"(a), "l"(b))

__device__ __forceinline__ float2 u64_as_f2(u64 v) {
    float2 f;
    memcpy(&f, &v, 8);
    return f;
}

__global__ void __launch_bounds__(256)
gemm2x_kernel(const float* __restrict__ A,
              const float* __restrict__ W0, const float* __restrict__ W1,
              float* __restrict__ out0, float* __restrict__ out1,
              int split, int n) {
    constexpr int BM = 128, K = 128, KC = 8;
    constexpr int NCHUNK = K / KC;     // 16
    constexpr int APAD = 2 * BM + 4;   // 260 floats per k-row (duplicated A)
    constexpr int WPAD = 128 + 4;      // 132 floats per k-row

    __shared__ float As[2][KC][APAD];
    __shared__ float Ws[2][KC][WPAD];

    int row0 = blockIdx.x * BM;
    int col0 = blockIdx.y * 128;
    int tid = threadIdx.x;
    int tx = tid & 15;                 // column group
    int ty = tid >> 4;                 // row group (8 rows)

    // per-thread load coordinates (one float4 of A, one of W per chunk)
    int lrow = tid >> 1;               // 0..127
    int lk4  = tid & 1;                // 0..1  (k = lk4*4 .. +3)
    const float* Arow = A + (size_t)(row0 + lrow) * K + lk4 * 4;
    bool a_ok = (row0 + lrow) < n;
    int vc = col0 + lrow;
    const float* Wrow = ((vc < split) ? (W0 + (size_t)vc * K)
                                      : (W1 + (size_t)(vc - split) * K)) + lk4 * 4;

    u64 acc[8][4];
#pragma unroll
    for (int i = 0; i < 8; i++)
#pragma unroll
        for (int j = 0; j < 4; j++) acc[i][j] = 0ull;

    float4 va = a_ok ? *reinterpret_cast<const float4*>(Arow) : make_float4(0.f, 0.f, 0.f, 0.f);
    float4 vw = *reinterpret_cast<const float4*>(Wrow);
    {
        float2* d0 = reinterpret_cast<float2*>(&As[0][lk4 * 4 + 0][2 * lrow]);
        float2* d1 = reinterpret_cast<float2*>(&As[0][lk4 * 4 + 1][2 * lrow]);
        float2* d2 = reinterpret_cast<float2*>(&As[0][lk4 * 4 + 2][2 * lrow]);
        float2* d3 = reinterpret_cast<float2*>(&As[0][lk4 * 4 + 3][2 * lrow]);
        *d0 = make_float2(va.x, va.x);
        *d1 = make_float2(va.y, va.y);
        *d2 = make_float2(va.z, va.z);
        *d3 = make_float2(va.w, va.w);
        Ws[0][lk4 * 4 + 0][lrow] = vw.x;
        Ws[0][lk4 * 4 + 1][lrow] = vw.y;
        Ws[0][lk4 * 4 + 2][lrow] = vw.z;
        Ws[0][lk4 * 4 + 3][lrow] = vw.w;
    }
    __syncthreads();

#pragma unroll
    for (int kc = 0; kc < NCHUNK; kc++) {
        int cur = kc & 1;
        // prefetch next chunk (LDG in flight during compute)
        if (kc < NCHUNK - 1) {
            int ko = (kc + 1) * KC;
            va = a_ok ? *reinterpret_cast<const float4*>(Arow + ko) : make_float4(0.f, 0.f, 0.f, 0.f);
            vw = *reinterpret_cast<const float4*>(Wrow + ko);
        }
        // compute current chunk
#pragma unroll
        for (int k = 0; k < KC; k++) {
            const ulonglong2* au = reinterpret_cast<const ulonglong2*>(&As[cur][k][16 * ty]);
            ulonglong2 a01 = au[0];
            ulonglong2 a23 = au[1];
            ulonglong2 a45 = au[2];
            ulonglong2 a67 = au[3];
            u64 ad[8] = {a01.x, a01.y, a23.x, a23.y, a45.x, a45.y, a67.x, a67.y};
            ulonglong2 b01 = *reinterpret_cast<const ulonglong2*>(&Ws[cur][k][4 * tx]);
            ulonglong2 b23 = *reinterpret_cast<const ulonglong2*>(&Ws[cur][k][64 + 4 * tx]);
            u64 bp[4] = {b01.x, b01.y, b23.x, b23.y};
#pragma unroll
            for (int i = 0; i < 8; i++) {
                FMA2(acc[i][0], ad[i], bp[0]);
                FMA2(acc[i][1], ad[i], bp[1]);
                FMA2(acc[i][2], ad[i], bp[2]);
                FMA2(acc[i][3], ad[i], bp[3]);
            }
        }
        // stage next chunk into the other buffer
        if (kc < NCHUNK - 1) {
            int nxt = cur ^ 1;
            float2* d0 = reinterpret_cast<float2*>(&As[nxt][lk4 * 4 + 0][2 * lrow]);
            float2* d1 = reinterpret_cast<float2*>(&As[nxt][lk4 * 4 + 1][2 * lrow]);
            float2* d2 = reinterpret_cast<float2*>(&As[nxt][lk4 * 4 + 2][2 * lrow]);
            float2* d3 = reinterpret_cast<float2*>(&As[nxt][lk4 * 4 + 3][2 * lrow]);
            *d0 = make_float2(va.x, va.x);
            *d1 = make_float2(va.y, va.y);
            *d2 = make_float2(va.z, va.z);
            *d3 = make_float2(va.w, va.w);
            Ws[nxt][lk4 * 4 + 0][lrow] = vw.x;
            Ws[nxt][lk4 * 4 + 1][lrow] = vw.y;
            Ws[nxt][lk4 * 4 + 2][lrow] = vw.z;
            Ws[nxt][lk4 * 4 + 3][lrow] = vw.w;
            __syncthreads();
        }
    }

    // ---- writeback ----
    int vcA = col0 + 4 * tx;
    int vcB = col0 + 64 + 4 * tx;
    float* baseA = (vcA < split) ? (out0 + vcA) : (out1 + (vcA - split));
    float* baseB = (vcB < split) ? (out0 + vcB) : (out1 + (vcB - split));
#pragma unroll
    for (int i = 0; i < 8; i++) {
        int r = row0 + ty * 8 + i;
        if (r >= n) continue;
        float2 a0 = u64_as_f2(acc[i][0]);
        float2 a1 = u64_as_f2(acc[i][1]);
        float2 b0 = u64_as_f2(acc[i][2]);
        float2 b1 = u64_as_f2(acc[i][3]);
        *reinterpret_cast<float4*>(baseA + (size_t)r * split) = make_float4(a0.x, a0.y, a1.x, a1.y);
        *reinterpret_cast<float4*>(baseB + (size_t)r * split) = make_float4(b0.x, b0.y, b1.x, b1.y);
    }
}

// ---------------- launch ----------------------------------------------------------
extern "C" void kernel_launch(void* const* d_in, const int* in_sizes, int n_in,
                              void* d_out, int out_size) {
    const float* x    = (const float*)d_in[0];
    const int*   ei   = (const int*)  d_in[1];
    const float* ew   = (const float*)d_in[2];
    // d_in[3] = node_type (unused by the reference)
    const float* W_l1 = (const float*)d_in[4];
    const float* b_l1 = (const float*)d_in[5];
    const float* W_r1 = (const float*)d_in[6];
    const float* W_l2 = (const float*)d_in[7];
    const float* b_l2 = (const float*)d_in[8];
    const float* W_r2 = (const float*)d_in[9];
    float* out = (float*)d_out;

    const int* src = ei;
    const int* dst = ei + N_EDGES;

    float *y1, *r1, *h, *y2, *r2;
    cudaGetSymbolAddress((void**)&y1, g_y1);
    cudaGetSymbolAddress((void**)&r1, g_r1);
    cudaGetSymbolAddress((void**)&h,  g_h);
    cudaGetSymbolAddress((void**)&y2, g_y2);
    cudaGetSymbolAddress((void**)&r2, g_r2);

    const int GB = (N_NODES + 127) / 128;           // 391

    // --- CSR build: ONE launch (zero + hist + scan + scatter, grid barrier) ---
    csr_kernel<<<CSR_BLOCKS, CSR_THREADS>>>(src, dst, ew);

    // --- layer 1: [W_l1; W_r1] stacked GEMM, gather-mean + fused epilogue ---
    gemm2x_kernel<<<dim3(GB, 2), 256>>>(x, W_l1, W_r1, y1, r1, 128, N_NODES);
    gather128_kernel<true><<<(N_NODES * 32 + 255) / 256, 256>>>(y1, r1, b_l1, h);

    // --- layer 2: [W_l2; W_r2] stacked GEMM (project to 64 before aggregating) ---
    gemm2x_kernel<<<dim3(GB, 1), 256>>>(h, W_l2, W_r2, y2, r2, 64, N_NODES);
    gather64_kernel<false><<<(N_NODES * 16 + 255) / 256, 256>>>(y2, r2, b_l2, out);
}